// round 13
// baseline (speedup 1.0000x reference)
#include <cuda_runtime.h>
#include <math.h>

#define BB   32
#define SS   256
#define CC   1024
#define DW   768
#define HH   256
#define G4   1024          // 4*H
#define NTAG 9
#define WIH_STRIDE 2816

// LSTM path smem (floats): smB 32768 | stage 2*4096 | slab 8*272 | mbar (4 floats)
// = 43140 floats = 172560 B. GEMM path uses first 36864 B. Launch with max:
#define LSTM_STAGE_F  32768
#define LSTM_SLAB_F   40960
#define LSTM_MBAR_F   43136
#define FUSED_SMEM_BYTES ((43136 * 4) + 16)   // 172560

// ---------------- scratch (static device globals; no allocations) ----------------
__device__ __align__(16) float g_v[BB*SS];                 // [b][s] broadcast scalar
__device__ __align__(16) float g_wsum[2*G4];               // [dir][gate] rowsum of Wih[:,768:]
__device__ __align__(16) float g_bias[2*G4];               // bih+bhh
__device__ __align__(16) float g_pre[(size_t)2*SS*BB*G4];  // [dir][t][b][g4]  (64 MB)
__device__ __align__(16) float g_hs[(size_t)2*SS*BB*HH];   // [dir][t][b][j]  (16 MB)
__device__ __align__(16) float g_wt[2*G4*HH];              // [dir][n'=j*4+gate][k] tf32 (2 MB)
__device__ float g_loss_sum;
__device__ float g_loss_cnt;
__device__ unsigned g_chunkcnt[16*32];                     // GEMM chunk counters, 128B padded

// ---------------- helpers ----------------
__device__ __forceinline__ float sigmoidf_(float x) { return 1.f / (1.f + __expf(-x)); }
__device__ __forceinline__ float tanh_fast(float x) {
    float e = __expf(-2.f * fabsf(x));
    float t = (1.f - e) / (1.f + e);
    return copysignf(t, x);
}
__device__ __forceinline__ unsigned ldacq(const unsigned* p) {
    unsigned v;
    asm volatile("ld.acquire.gpu.u32 %0, [%1];" : "=r"(v) : "l"(p));
    return v;
}
__device__ __forceinline__ void redrel(unsigned* p, unsigned v) {
    asm volatile("red.release.gpu.add.u32 [%0], %1;" :: "l"(p), "r"(v) : "memory");
}
__device__ __forceinline__ unsigned f2tf(float x) {
    unsigned r;
    asm("cvt.rna.tf32.f32 %0, %1;" : "=r"(r) : "f"(x));
    return r;
}
__device__ __forceinline__ float4 tf4(float4 v) {
    float4 o;
    o.x = __uint_as_float(f2tf(v.x));
    o.y = __uint_as_float(f2tf(v.y));
    o.z = __uint_as_float(f2tf(v.z));
    o.w = __uint_as_float(f2tf(v.w));
    return o;
}
__device__ __forceinline__ void mma_tf32(float* c, const unsigned* a, const unsigned* b) {
    asm volatile(
        "mma.sync.aligned.m16n8k8.row.col.f32.tf32.tf32.f32 "
        "{%0,%1,%2,%3}, {%4,%5,%6,%7}, {%8,%9}, {%0,%1,%2,%3};"
        : "+f"(c[0]), "+f"(c[1]), "+f"(c[2]), "+f"(c[3])
        : "r"(a[0]), "r"(a[1]), "r"(a[2]), "r"(a[3]), "r"(b[0]), "r"(b[1]));
}
// warp-local wait until chunk ck's 64 producer CTAs have signalled
__device__ __forceinline__ void chunk_wait(int ck) {
    if ((threadIdx.x & 31) == 0) {
        const unsigned* p = &g_chunkcnt[ck * 32];
        while (ldacq(p) < 64u) { }
    }
    __syncwarp();
}
// ---- cluster / DSMEM helpers ----
__device__ __forceinline__ unsigned smem_u32(const void* p) {
    unsigned a;
    asm("{ .reg .u64 t; cvta.to.shared.u64 t, %1; cvt.u32.u64 %0, t; }" : "=r"(a) : "l"(p));
    return a;
}
__device__ __forceinline__ unsigned mapa_rank(unsigned addr, unsigned rank) {
    unsigned r;
    asm("mapa.shared::cluster.u32 %0, %1, %2;" : "=r"(r) : "r"(addr), "r"(rank));
    return r;
}
__device__ __forceinline__ void st_cluster_f2(unsigned addr, float x, float y) {
    asm volatile("st.shared::cluster.v2.f32 [%0], {%1, %2};" :: "r"(addr), "f"(x), "f"(y) : "memory");
}
__device__ __forceinline__ void mbar_init(unsigned addr, unsigned cnt) {
    asm volatile("mbarrier.init.shared.b64 [%0], %1;" :: "r"(addr), "r"(cnt) : "memory");
}
__device__ __forceinline__ void mbar_arrive_cluster(unsigned remaddr) {
    asm volatile("mbarrier.arrive.release.cluster.shared::cluster.b64 _, [%0];"
                 :: "r"(remaddr) : "memory");
}
__device__ __forceinline__ void mbar_wait_parity(unsigned addr, unsigned parity) {
    asm volatile(
        "{\n\t.reg .pred P;\n\t"
        "LWAIT_%=:\n\t"
        "mbarrier.try_wait.parity.acquire.cluster.shared::cta.b64 P, [%0], %1;\n\t"
        "@!P bra LWAIT_%=;\n\t}"
        :: "r"(addr), "r"(parity) : "memory");
}
#define CLUSTER_SYNC() do { \
    asm volatile("barrier.cluster.arrive.aligned;" ::: "memory"); \
    asm volatile("barrier.cluster.wait.aligned;" ::: "memory"); \
} while (0)

// ---------------- kernel 1: segment-mean scalar v[b,s] ----------------
__global__ void __launch_bounds__(256) prep_v_kernel(const float* __restrict__ char_embs,
                                                     const int*   __restrict__ spans) {
    int tid  = threadIdx.x;
    int lane = tid & 31;
    int token = blockIdx.x * 8 + (tid >> 5);
    int st = spans[token * 2 + 0];
    int en = spans[token * 2 + 1];
    float s = 0.f;
    if (st >= 0) {
        int b = token >> 8;
        for (int c = st; c <= en; ++c) {
            const float* p = char_embs + ((size_t)(b * CC + c)) * DW;
            float acc = 0.f;
            for (int d = lane; d < DW; d += 32) acc += p[d];
            s += acc;
        }
        #pragma unroll
        for (int off = 16; off; off >>= 1) s += __shfl_xor_sync(0xffffffffu, s, off);
        s /= (768.f * (float)(en - st + 1));
    }
    if (lane == 0) g_v[token] = (st >= 0) ? s : 0.f;
}

// ---------------- kernel 2: wsum + bias + zero accumulators/counters ----------------
__global__ void __launch_bounds__(256) prep_w_kernel(
        const float* __restrict__ WihF, const float* __restrict__ WihB,
        const float* __restrict__ bihF, const float* __restrict__ bhhF,
        const float* __restrict__ bihB, const float* __restrict__ bhhB) {
    int tid  = threadIdx.x;
    int lane = tid & 31;
    int row  = blockIdx.x * 8 + (tid >> 5);     // 0..2047
    int dir  = row >> 10;
    int g    = row & 1023;
    const float* W = dir ? WihB : WihF;
    const float* wp = W + (size_t)g * WIH_STRIDE;
    float s = 0.f;
    for (int k = DW + lane; k < WIH_STRIDE; k += 32) s += wp[k];
    #pragma unroll
    for (int off = 16; off; off >>= 1) s += __shfl_xor_sync(0xffffffffu, s, off);
    if (lane == 0) {
        g_wsum[row] = s;
        g_bias[row] = dir ? (bihB[g] + bhhB[g]) : (bihF[g] + bhhF[g]);
    }
    if (blockIdx.x == 0) {
        if (tid == 0) { g_loss_sum = 0.f; g_loss_cnt = 0.f; }
        for (int i = tid; i < 16 * 32; i += 256) g_chunkcnt[i] = 0u;
    }
}

// ---------------- kernel 2b: reorder Whh -> g_wt[dir][n'=j*4+gate][k], tf32-rounded ----
__global__ void __launch_bounds__(256) prep_wt_kernel(const float* __restrict__ WhhF,
                                                      const float* __restrict__ WhhB) {
    int idx = blockIdx.x * 256 + threadIdx.x;   // 0 .. 524287
    int dir = idx >> 18;
    int r   = idx & 262143;
    int np  = r >> 8;          // n' 0..1023
    int k   = r & 255;
    int j = np >> 2, gate = np & 3;
    const float* W = dir ? WhhB : WhhF;
    float w = W[(size_t)(gate * 256 + j) * HH + k];
    g_wt[idx] = __uint_as_float(f2tf(w));
}

// ---------------- fused kernel: GEMM (blocks 32..1055) + LSTM (blocks 0..31) ----------------
// Whole grid launched with cluster dims (8,1,1): blocks 0..31 = 4 LSTM clusters
// (one per (dir,bs) group, rank = js); GEMM clusters are inert groupings.
// LSTM h exchange now via DSMEM: every thread pushes its 2 h values to all 8
// cluster CTAs' smem staging (mapa + st.shared::cluster) and arrives on each
// peer's parity mbarrier; consumers do a LOCAL try_wait + LDS. No global-memory
// sync in the recurrence at all. Double-buffer WAR safety: publish(ts+1) happens
// only after reading buf(ts) (per thread), so phase completion implies all reads.
__global__ void __launch_bounds__(256, 1) __cluster_dims__(8, 1, 1)
fused_kernel(const float* __restrict__ A,
             const float* __restrict__ WihF,
             const float* __restrict__ WihB) {
    extern __shared__ float smdyn[];

    if (blockIdx.x >= 32) {
        // =========================== GEMM path (unchanged math) ===========================
        float* As = smdyn;               // [128*36]
        float* Bs = smdyn + 128 * 36;    // [128*36]
        int bid2 = blockIdx.x - 32;
        int gx = bid2 & 15;
        int gy = bid2 >> 4;            // 0..63
        int pos = gy >> 2;             // 0..15 position in chunk order
        int tb  = gy & 3;              // batch group: b in [tb*8, tb*8+8)
        int chunk = (pos & 1) ? (15 - (pos >> 1)) : (pos >> 1);

        int tid  = threadIdx.x;
        int lane = tid & 31;
        int warp = tid >> 5;
        int wm = warp >> 2;            // 0..1
        int wn = warp & 3;             // 0..3
        int nBase = gx * 128;

        int lrow = tid >> 3;           // 0..31
        int lq   = tid & 7;            // 0..7 -> col lq*4

        const float* aPtr[4];
        const float* bPtr[4];
        #pragma unroll
        for (int p = 0; p < 4; ++p) {
            int r  = lrow + p * 32;
            int rb = tb * 8 + (r & 7);
            int rs = chunk * 16 + (r >> 3);
            aPtr[p] = A + (size_t)(rb * 256 + rs) * DW + lq * 4;
            int n = nBase + r;
            const float* W = (n >= G4) ? WihB : WihF;
            bPtr[p] = W + (size_t)(n & 1023) * WIH_STRIDE + lq * 4;
        }

        float acc[4][4][4];
        #pragma unroll
        for (int mt = 0; mt < 4; ++mt)
            #pragma unroll
            for (int nt = 0; nt < 4; ++nt)
                #pragma unroll
                for (int q = 0; q < 4; ++q) acc[mt][nt][q] = 0.f;

        float4 ra[4], rb4[4];
        #pragma unroll
        for (int p = 0; p < 4; ++p) {
            ra[p]  = *(const float4*)aPtr[p];
            rb4[p] = *(const float4*)bPtr[p];
        }

        for (int kt = 0; kt < DW; kt += 32) {
            if (kt) __syncthreads();
            #pragma unroll
            for (int p = 0; p < 4; ++p) {
                int r = lrow + p * 32;
                *(float4*)&As[r * 36 + lq * 4] = tf4(ra[p]);
                *(float4*)&Bs[r * 36 + lq * 4] = tf4(rb4[p]);
            }
            __syncthreads();
            if (kt + 32 < DW) {
                #pragma unroll
                for (int p = 0; p < 4; ++p) {
                    ra[p]  = *(const float4*)(aPtr[p] + kt + 32);
                    rb4[p] = *(const float4*)(bPtr[p] + kt + 32);
                }
            }
            int q  = lane & 3;
            int gp = lane >> 2;
            #pragma unroll
            for (int kc = 0; kc < 32; kc += 8) {
                unsigned afr[4][4], bfr[4][2];
                #pragma unroll
                for (int mt = 0; mt < 4; ++mt) {
                    int r = wm * 64 + mt * 16 + gp;
                    afr[mt][0] = __float_as_uint(As[r * 36 + kc + q]);
                    afr[mt][1] = __float_as_uint(As[(r + 8) * 36 + kc + q]);
                    afr[mt][2] = __float_as_uint(As[r * 36 + kc + q + 4]);
                    afr[mt][3] = __float_as_uint(As[(r + 8) * 36 + kc + q + 4]);
                }
                #pragma unroll
                for (int nt = 0; nt < 4; ++nt) {
                    int c = wn * 32 + nt * 8 + gp;
                    bfr[nt][0] = __float_as_uint(Bs[c * 36 + kc + q]);
                    bfr[nt][1] = __float_as_uint(Bs[c * 36 + kc + q + 4]);
                }
                #pragma unroll
                for (int mt = 0; mt < 4; ++mt)
                    #pragma unroll
                    for (int nt = 0; nt < 4; ++nt)
                        mma_tf32(acc[mt][nt], afr[mt], bfr[nt]);
            }
        }

        #pragma unroll
        for (int mt = 0; mt < 4; ++mt) {
            int base = wm * 64 + mt * 16;
            int s0 = chunk * 16 + (base >> 3);
            int bb = tb * 8 + (lane >> 2);
            float v0 = g_v[bb * 256 + s0];
            float v1 = g_v[bb * 256 + s0 + 1];
            #pragma unroll
            for (int nt = 0; nt < 4; ++nt) {
                int n0  = nBase + wn * 32 + nt * 8 + 2 * (lane & 3);
                int dir = n0 >> 10;
                int g   = n0 & 1023;
                float2 w2  = *(const float2*)&g_wsum[n0];
                float2 bi2 = *(const float2*)&g_bias[n0];
                size_t base0 = (((size_t)dir * SS + s0) * BB + bb) * G4 + g;
                float2 o0 = make_float2(acc[mt][nt][0] + v0 * w2.x + bi2.x,
                                        acc[mt][nt][1] + v0 * w2.y + bi2.y);
                *(float2*)&g_pre[base0] = o0;
                size_t base1 = (((size_t)dir * SS + (s0 + 1)) * BB + bb) * G4 + g;
                float2 o1 = make_float2(acc[mt][nt][2] + v1 * w2.x + bi2.x,
                                        acc[mt][nt][3] + v1 * w2.y + bi2.y);
                *(float2*)&g_pre[base1] = o1;
            }
        }

        __syncthreads();
        if (tid == 0) redrel(&g_chunkcnt[chunk * 32], 1u);
        return;
    }

    // =========================== LSTM path (DSMEM exchange) ===========================
    float* smB = smdyn;                         // [16 ntL][32 kt][32 lane][2]
    float* slab = smdyn + LSTM_SLAB_F;          // per-warp [16 col][17]

    int bid = blockIdx.x;
    int dir = bid >> 4;
    int bs  = (bid >> 3) & 1;
    int js  = bid & 7;                          // == cluster rank
    int tid = threadIdx.x;
    int lane = tid & 31;
    int w    = tid >> 5;

    unsigned stage_u32 = smem_u32(smdyn + LSTM_STAGE_F);
    unsigned mbar_u32  = smem_u32(smdyn + LSTM_MBAR_F);

    // ---- init mbarriers (2048 arrivals = 8 CTAs x 256 threads per phase) ----
    if (tid == 0) {
        mbar_init(mbar_u32 + 0, 2048u);
        mbar_init(mbar_u32 + 8, 2048u);
        asm volatile("fence.mbarrier_init.release.cluster;" ::: "memory");
    }

    // ---- Whh B-fragments -> smem, frag-ordered (loaded once) ----
    {
        const float* Wt = g_wt + (size_t)dir * G4 * HH;
        for (int idx = tid; idx < 32768; idx += 256) {
            int h  = idx & 1;
            int ln = (idx >> 1) & 31;
            int kt = (idx >> 6) & 31;
            int ntL = idx >> 11;
            int n = js * 128 + ntL * 8 + (ln >> 2);
            int k = kt * 8 + (ln & 3) + h * 4;
            smB[idx] = Wt[(size_t)n * HH + k];
        }
    }
    __syncthreads();
    CLUSTER_SYNC();    // mbarriers + peer CTAs valid before any remote store/arrive

    // ---- cell identity: warp w owns j in [js*32 + w*4, +4); lane (p, rloc) ----
    int p    = lane & 3;
    int rloc = lane >> 2;           // 0..7
    int j    = js * 32 + w * 4 + p;
    int b0   = bs * 16 + rloc;
    int b1   = b0 + 8;

    int ktp   = js * 4 + (w >> 1);
    int word0 = ktp * 128 + lane * 4 + ((w & 1) << 1);

    const float* preD = g_pre + (size_t)dir * SS * BB * G4;
    float* myslab = slab + w * 272;
    const float2* smB2 = (const float2*)smB;

    int ph0 = 0, ph1 = 0;           // per-thread mbarrier phase parity
    float c0 = 0.f, c1 = 0.f;
    float pr[8];
    {
        int t0 = dir ? (SS - 1) : 0;
        chunk_wait(t0 >> 4);
        const float* pp0 = preD + ((size_t)t0 * BB + b0) * G4;
        const float* pp1 = preD + ((size_t)t0 * BB + b1) * G4;
        #pragma unroll
        for (int g = 0; g < 4; ++g) { pr[g] = pp0[g * 256 + j]; pr[4 + g] = pp1[g * 256 + j]; }
    }

    for (int ts = 0; ts < SS; ++ts) {
        int t  = dir ? (SS - 1 - ts) : ts;
        int tn = dir ? (SS - 2 - ts) : (ts + 1);

        // gate next GEMM chunk (once per 16 steps), then prefetch next pre
        if (ts + 1 < SS && (ts & 15) == 15) chunk_wait(tn >> 4);
        float np[8];
        if (ts + 1 < SS) {
            const float* pn0 = preD + ((size_t)tn * BB + b0) * G4;
            const float* pn1 = preD + ((size_t)tn * BB + b1) * G4;
            #pragma unroll
            for (int g = 0; g < 4; ++g) { np[g] = pn0[g * 256 + j]; np[4 + g] = pn1[g * 256 + j]; }
        }

        float acc[2][4];
        #pragma unroll
        for (int nt = 0; nt < 2; ++nt)
            #pragma unroll
            for (int q = 0; q < 4; ++q) acc[nt][q] = 0.f;

        if (ts > 0) {
            // local mbarrier wait (acquire, cluster scope)
            int par = ts & 1;
            if (par) { mbar_wait_parity(mbar_u32 + 8, (unsigned)ph1); ph1 ^= 1; }
            else     { mbar_wait_parity(mbar_u32 + 0, (unsigned)ph0); ph0 ^= 1; }

            // matvec: A-fragments from LOCAL smem staging
            const float4* hf = (const float4*)(smdyn + LSTM_STAGE_F + par * 4096);
            #pragma unroll
            for (int kt = 0; kt < 32; ++kt) {
                float4 a = hf[kt * 32 + lane];
                unsigned ar[4] = {__float_as_uint(a.x), __float_as_uint(a.y),
                                  __float_as_uint(a.z), __float_as_uint(a.w)};
                float2 bb0 = smB2[((w * 2 + 0) * 32 + kt) * 32 + lane];
                float2 bb1 = smB2[((w * 2 + 1) * 32 + kt) * 32 + lane];
                unsigned br0[2] = {__float_as_uint(bb0.x), __float_as_uint(bb0.y)};
                unsigned br1[2] = {__float_as_uint(bb1.x), __float_as_uint(bb1.y)};
                mma_tf32(acc[0], ar, br0);
                mma_tf32(acc[1], ar, br1);
            }
        }

        // per-warp gate gather (C-fragment -> cells)
        #pragma unroll
        for (int nt = 0; nt < 2; ++nt)
            #pragma unroll
            for (int q = 0; q < 4; ++q) {
                int col = nt * 8 + ((lane & 3) << 1) + (q & 1);
                int row = (lane >> 2) + ((q & 2) ? 8 : 0);
                myslab[col * 17 + row] = acc[nt][q];
            }
        __syncwarp();

        float h0, h1;
        {
            float g0 = myslab[(p * 4 + 0) * 17 + rloc] + pr[0];
            float g1 = myslab[(p * 4 + 1) * 17 + rloc] + pr[1];
            float g2 = myslab[(p * 4 + 2) * 17 + rloc] + pr[2];
            float g3 = myslab[(p * 4 + 3) * 17 + rloc] + pr[3];
            c0 = sigmoidf_(g1) * c0 + sigmoidf_(g0) * tanh_fast(g2);
            h0 = sigmoidf_(g3) * tanh_fast(c0);
        }
        {
            float g0 = myslab[(p * 4 + 0) * 17 + rloc + 8] + pr[4];
            float g1 = myslab[(p * 4 + 1) * 17 + rloc + 8] + pr[5];
            float g2 = myslab[(p * 4 + 2) * 17 + rloc + 8] + pr[6];
            float g3 = myslab[(p * 4 + 3) * 17 + rloc + 8] + pr[7];
            c1 = sigmoidf_(g1) * c1 + sigmoidf_(g0) * tanh_fast(g2);
            h1 = sigmoidf_(g3) * tanh_fast(c1);
        }

        // ---- publish h(ts+1) to ALL 8 cluster CTAs via DSMEM + arrive ----
        {
            int par = (ts + 1) & 1;
            float h0t = __uint_as_float(f2tf(h0));
            float h1t = __uint_as_float(f2tf(h1));
            unsigned waddr = stage_u32 + (unsigned)((par * 4096 + word0) * 4);
            #pragma unroll
            for (int r = 0; r < 8; ++r)
                st_cluster_f2(mapa_rank(waddr, (unsigned)r), h0t, h1t);
            unsigned aaddr = mbar_u32 + (unsigned)(par * 8);
            #pragma unroll
            for (int r = 0; r < 8; ++r)
                mbar_arrive_cluster(mapa_rank(aaddr, (unsigned)r));
        }

        // off-critical-path: g_hs for emissions
        g_hs[(((size_t)dir * SS + t) * BB + b0) * HH + j] = h0;
        g_hs[(((size_t)dir * SS + t) * BB + b1) * HH + j] = h1;

        #pragma unroll
        for (int g = 0; g < 8; ++g) pr[g] = np[g];
    }

    CLUSTER_SYNC();    // no CTA exits while peers may still store/arrive into it
}

// ---------------- kernel 5: emissions + NLL partial sums ----------------
__global__ void __launch_bounds__(256) emis_kernel(const int* __restrict__ labels,
                                                   const float* __restrict__ Wtag,
                                                   const float* __restrict__ btag) {
    __shared__ float wt[NTAG * 512];
    __shared__ float bt[NTAG];
    int tid = threadIdx.x;
    for (int i = tid; i < NTAG * 512; i += 256) wt[i] = Wtag[i];
    if (tid < NTAG) bt[tid] = btag[tid];
    __syncthreads();

    int idx = blockIdx.x * 256 + tid;      // 0..8191
    int b = idx >> 8, t = idx & 255;

    float acc[NTAG];
    #pragma unroll
    for (int q = 0; q < NTAG; ++q) acc[q] = bt[q];

    #pragma unroll
    for (int part = 0; part < 2; ++part) {
        const float* hp = g_hs + (((size_t)part * SS + t) * BB + b) * HH;
        for (int k4 = 0; k4 < HH; k4 += 4) {
            float4 h4 = *(const float4*)&hp[k4];
            #pragma unroll
            for (int q = 0; q < NTAG; ++q) {
                const float* w = &wt[q * 512 + part * HH + k4];
                acc[q] += h4.x * w[0] + h4.y * w[1] + h4.z * w[2] + h4.w * w[3];
            }
        }
    }

    int lab = labels[idx];
    float nll = 0.f, cnt = 0.f;
    if (lab != -100) {
        int lc = lab < 0 ? 0 : lab;
        float m = acc[0];
        #pragma unroll
        for (int q = 1; q < NTAG; ++q) m = fmaxf(m, acc[q]);
        float s = 0.f;
        #pragma unroll
        for (int q = 0; q < NTAG; ++q) s += __expf(acc[q] - m);
        nll = m + logf(s) - acc[lc];
        cnt = 1.f;
    }
    #pragma unroll
    for (int off = 16; off; off >>= 1) {
        nll += __shfl_xor_sync(0xffffffffu, nll, off);
        cnt += __shfl_xor_sync(0xffffffffu, cnt, off);
    }
    if ((tid & 31) == 0) {
        atomicAdd(&g_loss_sum, nll);
        atomicAdd(&g_loss_cnt, cnt);
    }
}

// ---------------- kernel 6: finalize ----------------
__global__ void finalize_kernel(float* out) {
    out[0] = g_loss_sum / fmaxf(g_loss_cnt, 1.f);
}

// ---------------- launch ----------------
extern "C" void kernel_launch(void* const* d_in, const int* in_sizes, int n_in,
                              void* d_out, int out_size) {
    const float* word_embs = (const float*)d_in[0];
    const float* char_embs = (const float*)d_in[1];
    const int*   spans     = (const int*)  d_in[2];
    const int*   labels    = (const int*)  d_in[3];
    const float* WihF      = (const float*)d_in[4];
    const float* WhhF      = (const float*)d_in[5];
    const float* bihF      = (const float*)d_in[6];
    const float* bhhF      = (const float*)d_in[7];
    const float* WihB      = (const float*)d_in[8];
    const float* WhhB      = (const float*)d_in[9];
    const float* bihB      = (const float*)d_in[10];
    const float* bhhB      = (const float*)d_in[11];
    const float* Wtag      = (const float*)d_in[12];
    const float* btag      = (const float*)d_in[13];
    float* out = (float*)d_out;

    cudaFuncSetAttribute(fused_kernel, cudaFuncAttributeMaxDynamicSharedMemorySize, FUSED_SMEM_BYTES);

    prep_v_kernel<<<1024, 256>>>(char_embs, spans);
    prep_w_kernel<<<256, 256>>>(WihF, WihB, bihF, bhhF, bihB, bhhB);
    prep_wt_kernel<<<2048, 256>>>(WhhF, WhhB);
    fused_kernel<<<1056, 256, FUSED_SMEM_BYTES>>>(word_embs, WihF, WihB);
    emis_kernel<<<32, 256>>>(labels, Wtag, btag);
    finalize_kernel<<<1, 1>>>(out);
}

// round 14
// speedup vs baseline: 2.2251x; 2.2251x over previous
#include <cuda_runtime.h>
#include <math.h>

#define BB   32
#define SS   256
#define CC   1024
#define DW   768
#define HH   256
#define G4   1024          // 4*H
#define NTAG 9
#define WIH_STRIDE 2816

// LSTM path: smB 32768 floats (128KB) + slab 8*272 floats; GEMM path: 36864 B. Max:
#define FUSED_SMEM_BYTES ((32768 + 8*272) * 4)   // 139776

// ---------------- scratch (static device globals; no allocations) ----------------
__device__ __align__(16) float g_v[BB*SS];                 // [b][s] broadcast scalar
__device__ __align__(16) float g_wsum[2*G4];               // [dir][gate] rowsum of Wih[:,768:]
__device__ __align__(16) float g_bias[2*G4];               // bih+bhh
__device__ __align__(16) float g_pre[(size_t)2*SS*BB*G4];  // [dir][t][b][g4]  (64 MB)
__device__ __align__(16) float g_hs[(size_t)2*SS*BB*HH];   // [dir][t][b][j]  (16 MB)
__device__ __align__(16) float g_wt[2*G4*HH];              // [dir][n'=j*4+gate][k] tf32 (2 MB)
__device__ __align__(16) unsigned g_hfrag2[2*2*2*4096];    // [dir][bs][parity][tagged tf32 words]
__device__ float g_loss_sum;
__device__ float g_loss_cnt;
__device__ unsigned g_chunkcnt[16*32];                     // GEMM chunk counters, 128B padded

// ---------------- helpers ----------------
__device__ __forceinline__ float sigmoidf_(float x) { return 1.f / (1.f + __expf(-x)); }
__device__ __forceinline__ float tanh_fast(float x) {
    float e = __expf(-2.f * fabsf(x));
    float t = (1.f - e) / (1.f + e);
    return copysignf(t, x);
}
__device__ __forceinline__ unsigned ldacq(const unsigned* p) {
    unsigned v;
    asm volatile("ld.acquire.gpu.u32 %0, [%1];" : "=r"(v) : "l"(p));
    return v;
}
__device__ __forceinline__ void redrel(unsigned* p, unsigned v) {
    asm volatile("red.release.gpu.add.u32 [%0], %1;" :: "l"(p), "r"(v) : "memory");
}
__device__ __forceinline__ unsigned f2tf(float x) {
    unsigned r;
    asm("cvt.rna.tf32.f32 %0, %1;" : "=r"(r) : "f"(x));
    return r;
}
__device__ __forceinline__ float4 tf4(float4 v) {
    float4 o;
    o.x = __uint_as_float(f2tf(v.x));
    o.y = __uint_as_float(f2tf(v.y));
    o.z = __uint_as_float(f2tf(v.z));
    o.w = __uint_as_float(f2tf(v.w));
    return o;
}
__device__ __forceinline__ void mma_tf32(float* c, const unsigned* a, const unsigned* b) {
    asm volatile(
        "mma.sync.aligned.m16n8k8.row.col.f32.tf32.tf32.f32 "
        "{%0,%1,%2,%3}, {%4,%5,%6,%7}, {%8,%9}, {%0,%1,%2,%3};"
        : "+f"(c[0]), "+f"(c[1]), "+f"(c[2]), "+f"(c[3])
        : "r"(a[0]), "r"(a[1]), "r"(a[2]), "r"(a[3]), "r"(b[0]), "r"(b[1]));
}
// volatile L2 load/store (prevent CSE/hoist in retry loops)
__device__ __forceinline__ uint4 ldcg_v4(const uint4* p) {
    uint4 v;
    asm volatile("ld.global.cg.v4.u32 {%0,%1,%2,%3}, [%4];"
                 : "=r"(v.x), "=r"(v.y), "=r"(v.z), "=r"(v.w) : "l"(p) : "memory");
    return v;
}
__device__ __forceinline__ void stcg_v2(unsigned* p, unsigned x, unsigned y) {
    asm volatile("st.global.cg.v2.u32 [%0], {%1,%2};" :: "l"(p), "r"(x), "r"(y) : "memory");
}
// warp-local wait until chunk ck's 64 producer CTAs have signalled
__device__ __forceinline__ void chunk_wait(int ck) {
    if ((threadIdx.x & 31) == 0) {
        const unsigned* p = &g_chunkcnt[ck * 32];
        while (ldacq(p) < 64u) { }
    }
    __syncwarp();
}

// ---------------- kernel 1: segment-mean scalar v[b,s] ----------------
__global__ void __launch_bounds__(256) prep_v_kernel(const float* __restrict__ char_embs,
                                                     const int*   __restrict__ spans) {
    int tid  = threadIdx.x;
    int lane = tid & 31;
    int token = blockIdx.x * 8 + (tid >> 5);
    int st = spans[token * 2 + 0];
    int en = spans[token * 2 + 1];
    float s = 0.f;
    if (st >= 0) {
        int b = token >> 8;
        for (int c = st; c <= en; ++c) {
            const float* p = char_embs + ((size_t)(b * CC + c)) * DW;
            float acc = 0.f;
            for (int d = lane; d < DW; d += 32) acc += p[d];
            s += acc;
        }
        #pragma unroll
        for (int off = 16; off; off >>= 1) s += __shfl_xor_sync(0xffffffffu, s, off);
        s /= (768.f * (float)(en - st + 1));
    }
    if (lane == 0) g_v[token] = (st >= 0) ? s : 0.f;
}

// ---------------- kernel 2: wsum + bias + zero accumulators/counters ----------------
__global__ void __launch_bounds__(256) prep_w_kernel(
        const float* __restrict__ WihF, const float* __restrict__ WihB,
        const float* __restrict__ bihF, const float* __restrict__ bhhF,
        const float* __restrict__ bihB, const float* __restrict__ bhhB) {
    int tid  = threadIdx.x;
    int lane = tid & 31;
    int row  = blockIdx.x * 8 + (tid >> 5);     // 0..2047
    int dir  = row >> 10;
    int g    = row & 1023;
    const float* W = dir ? WihB : WihF;
    const float* wp = W + (size_t)g * WIH_STRIDE;
    float s = 0.f;
    for (int k = DW + lane; k < WIH_STRIDE; k += 32) s += wp[k];
    #pragma unroll
    for (int off = 16; off; off >>= 1) s += __shfl_xor_sync(0xffffffffu, s, off);
    if (lane == 0) {
        g_wsum[row] = s;
        g_bias[row] = dir ? (bihB[g] + bhhB[g]) : (bihF[g] + bhhF[g]);
    }
    if (blockIdx.x == 0) {
        if (tid == 0) { g_loss_sum = 0.f; g_loss_cnt = 0.f; }
        for (int i = tid; i < 16 * 32; i += 256) g_chunkcnt[i] = 0u;
    }
}

// ---------------- kernel 2b: reorder Whh -> g_wt[dir][n'=j*4+gate][k], tf32-rounded ----
__global__ void __launch_bounds__(256) prep_wt_kernel(const float* __restrict__ WhhF,
                                                      const float* __restrict__ WhhB) {
    int idx = blockIdx.x * 256 + threadIdx.x;   // 0 .. 524287
    int dir = idx >> 18;
    int r   = idx & 262143;
    int np  = r >> 8;          // n' 0..1023
    int k   = r & 255;
    int j = np >> 2, gate = np & 3;
    const float* W = dir ? WhhB : WhhF;
    float w = W[(size_t)(gate * 256 + j) * HH + k];
    g_wt[idx] = __uint_as_float(f2tf(w));
}

// ---------------- fused kernel: GEMM (blocks 32..1055) + LSTM (blocks 0..31) ----------------
// Dynamic smem aliased per path (GEMM 36864 B; LSTM 139776 B).
// LSTM exchange (NEW): tag-in-mantissa. h published as tf32 words whose low 13
// bits (outside the tf32 field, ignored by mma) carry tag = ts+1. Consumers
// speculatively load A-fragments and spin per-lane until all tags == ts.
// No flags, no fences, no __syncthreads in the step loop. Double-buffered by
// step parity; WAR induction holds lane-wise via data dependence.
__global__ void __launch_bounds__(256, 1) fused_kernel(const float* __restrict__ A,
                                                       const float* __restrict__ WihF,
                                                       const float* __restrict__ WihB) {
    extern __shared__ float smdyn[];

    if (blockIdx.x >= 32) {
        // =========================== GEMM path (unchanged) ===========================
        float* As = smdyn;               // [128*36]
        float* Bs = smdyn + 128 * 36;    // [128*36]
        int bid2 = blockIdx.x - 32;
        int gx = bid2 & 15;
        int gy = bid2 >> 4;            // 0..63
        int pos = gy >> 2;             // 0..15 position in chunk order
        int tb  = gy & 3;              // batch group: b in [tb*8, tb*8+8)
        int chunk = (pos & 1) ? (15 - (pos >> 1)) : (pos >> 1);

        int tid  = threadIdx.x;
        int lane = tid & 31;
        int warp = tid >> 5;
        int wm = warp >> 2;            // 0..1
        int wn = warp & 3;             // 0..3
        int nBase = gx * 128;

        int lrow = tid >> 3;           // 0..31
        int lq   = tid & 7;            // 0..7 -> col lq*4

        const float* aPtr[4];
        const float* bPtr[4];
        #pragma unroll
        for (int p = 0; p < 4; ++p) {
            int r  = lrow + p * 32;
            int rb = tb * 8 + (r & 7);
            int rs = chunk * 16 + (r >> 3);
            aPtr[p] = A + (size_t)(rb * 256 + rs) * DW + lq * 4;
            int n = nBase + r;
            const float* W = (n >= G4) ? WihB : WihF;
            bPtr[p] = W + (size_t)(n & 1023) * WIH_STRIDE + lq * 4;
        }

        float acc[4][4][4];
        #pragma unroll
        for (int mt = 0; mt < 4; ++mt)
            #pragma unroll
            for (int nt = 0; nt < 4; ++nt)
                #pragma unroll
                for (int q = 0; q < 4; ++q) acc[mt][nt][q] = 0.f;

        float4 ra[4], rb4[4];
        #pragma unroll
        for (int p = 0; p < 4; ++p) {
            ra[p]  = *(const float4*)aPtr[p];
            rb4[p] = *(const float4*)bPtr[p];
        }

        for (int kt = 0; kt < DW; kt += 32) {
            if (kt) __syncthreads();
            #pragma unroll
            for (int p = 0; p < 4; ++p) {
                int r = lrow + p * 32;
                *(float4*)&As[r * 36 + lq * 4] = tf4(ra[p]);
                *(float4*)&Bs[r * 36 + lq * 4] = tf4(rb4[p]);
            }
            __syncthreads();
            if (kt + 32 < DW) {
                #pragma unroll
                for (int p = 0; p < 4; ++p) {
                    ra[p]  = *(const float4*)(aPtr[p] + kt + 32);
                    rb4[p] = *(const float4*)(bPtr[p] + kt + 32);
                }
            }
            int q  = lane & 3;
            int gp = lane >> 2;
            #pragma unroll
            for (int kc = 0; kc < 32; kc += 8) {
                unsigned afr[4][4], bfr[4][2];
                #pragma unroll
                for (int mt = 0; mt < 4; ++mt) {
                    int r = wm * 64 + mt * 16 + gp;
                    afr[mt][0] = __float_as_uint(As[r * 36 + kc + q]);
                    afr[mt][1] = __float_as_uint(As[(r + 8) * 36 + kc + q]);
                    afr[mt][2] = __float_as_uint(As[r * 36 + kc + q + 4]);
                    afr[mt][3] = __float_as_uint(As[(r + 8) * 36 + kc + q + 4]);
                }
                #pragma unroll
                for (int nt = 0; nt < 4; ++nt) {
                    int c = wn * 32 + nt * 8 + gp;
                    bfr[nt][0] = __float_as_uint(Bs[c * 36 + kc + q]);
                    bfr[nt][1] = __float_as_uint(Bs[c * 36 + kc + q + 4]);
                }
                #pragma unroll
                for (int mt = 0; mt < 4; ++mt)
                    #pragma unroll
                    for (int nt = 0; nt < 4; ++nt)
                        mma_tf32(acc[mt][nt], afr[mt], bfr[nt]);
            }
        }

        #pragma unroll
        for (int mt = 0; mt < 4; ++mt) {
            int base = wm * 64 + mt * 16;
            int s0 = chunk * 16 + (base >> 3);
            int bb = tb * 8 + (lane >> 2);
            float v0 = g_v[bb * 256 + s0];
            float v1 = g_v[bb * 256 + s0 + 1];
            #pragma unroll
            for (int nt = 0; nt < 4; ++nt) {
                int n0  = nBase + wn * 32 + nt * 8 + 2 * (lane & 3);
                int dir = n0 >> 10;
                int g   = n0 & 1023;
                float2 w2  = *(const float2*)&g_wsum[n0];
                float2 bi2 = *(const float2*)&g_bias[n0];
                size_t base0 = (((size_t)dir * SS + s0) * BB + bb) * G4 + g;
                float2 o0 = make_float2(acc[mt][nt][0] + v0 * w2.x + bi2.x,
                                        acc[mt][nt][1] + v0 * w2.y + bi2.y);
                *(float2*)&g_pre[base0] = o0;
                size_t base1 = (((size_t)dir * SS + (s0 + 1)) * BB + bb) * G4 + g;
                float2 o1 = make_float2(acc[mt][nt][2] + v1 * w2.x + bi2.x,
                                        acc[mt][nt][3] + v1 * w2.y + bi2.y);
                *(float2*)&g_pre[base1] = o1;
            }
        }

        __syncthreads();
        if (tid == 0) redrel(&g_chunkcnt[chunk * 32], 1u);
        return;
    }

    // =========================== LSTM path (tagged exchange) ===========================
    float* smB  = smdyn;            // [16 ntL][32 kt][32 lane][2] = 32768 floats
    float* slab = smdyn + 32768;    // per-warp [16 col][17] gather

    int bid = blockIdx.x;
    int dir = bid >> 4;
    int bs  = (bid >> 3) & 1;
    int js  = bid & 7;
    int tid = threadIdx.x;
    int lane = tid & 31;
    int w    = tid >> 5;

    // ---- Whh B-fragments -> smem, frag-ordered (loaded once) ----
    {
        const float* Wt = g_wt + (size_t)dir * G4 * HH;
        for (int idx = tid; idx < 32768; idx += 256) {
            int h  = idx & 1;
            int ln = (idx >> 1) & 31;
            int kt = (idx >> 6) & 31;
            int ntL = idx >> 11;
            int n = js * 128 + ntL * 8 + (ln >> 2);
            int k = kt * 8 + (ln & 3) + h * 4;
            smB[idx] = Wt[(size_t)n * HH + k];
        }
    }
    __syncthreads();

    // ---- cell identity: warp w owns j in [js*32 + w*4, +4); lane (p, rloc) ----
    int p    = lane & 3;
    int rloc = lane >> 2;           // 0..7
    int j    = js * 32 + w * 4 + p;
    int b0   = bs * 16 + rloc;
    int b1   = b0 + 8;

    int ktp   = js * 4 + (w >> 1);
    int word0 = ktp * 128 + lane * 4 + ((w & 1) << 1);

    const float* preD = g_pre + (size_t)dir * SS * BB * G4;
    unsigned* stageD = g_hfrag2 + (size_t)(dir * 2 + bs) * 2 * 4096;
    float* myslab = slab + w * 272;
    const float2* smB2 = (const float2*)smB;

    float c0 = 0.f, c1 = 0.f;
    float pr[8];
    {
        int t0 = dir ? (SS - 1) : 0;
        chunk_wait(t0 >> 4);
        const float* pp0 = preD + ((size_t)t0 * BB + b0) * G4;
        const float* pp1 = preD + ((size_t)t0 * BB + b1) * G4;
        #pragma unroll
        for (int g = 0; g < 4; ++g) { pr[g] = pp0[g * 256 + j]; pr[4 + g] = pp1[g * 256 + j]; }
    }

    for (int ts = 0; ts < SS; ++ts) {
        int t  = dir ? (SS - 1 - ts) : ts;
        int tn = dir ? (SS - 2 - ts) : (ts + 1);

        // gate next GEMM chunk (once per 16 steps), then prefetch next pre
        if (ts + 1 < SS && (ts & 15) == 15) chunk_wait(tn >> 4);
        float np[8];
        if (ts + 1 < SS) {
            const float* pn0 = preD + ((size_t)tn * BB + b0) * G4;
            const float* pn1 = preD + ((size_t)tn * BB + b1) * G4;
            #pragma unroll
            for (int g = 0; g < 4; ++g) { np[g] = pn0[g * 256 + j]; np[4 + g] = pn1[g * 256 + j]; }
        }

        float acc[2][4];
        #pragma unroll
        for (int nt = 0; nt < 2; ++nt)
            #pragma unroll
            for (int q = 0; q < 4; ++q) acc[nt][q] = 0.f;

        if (ts > 0) {
            // matvec with self-validating A-fragments: spin until all tags == ts
            const uint4* hf = (const uint4*)(stageD + (ts & 1) * 4096);
            unsigned expect = (unsigned)ts;
            #pragma unroll
            for (int grp = 0; grp < 4; ++grp) {
                uint4 av[8];
                #pragma unroll
                for (int i = 0; i < 8; ++i)
                    av[i] = ldcg_v4(hf + grp * 256 + i * 32 + lane);
                for (;;) {
                    unsigned bad = 0u;
                    #pragma unroll
                    for (int i = 0; i < 8; ++i)
                        bad |= (av[i].x ^ expect) | (av[i].y ^ expect) |
                               (av[i].z ^ expect) | (av[i].w ^ expect);
                    if (!(bad & 0x1FFFu)) break;
                    #pragma unroll
                    for (int i = 0; i < 8; ++i)
                        av[i] = ldcg_v4(hf + grp * 256 + i * 32 + lane);
                }
                #pragma unroll
                for (int i = 0; i < 8; ++i) {
                    int kt = grp * 8 + i;
                    unsigned ar[4] = {av[i].x, av[i].y, av[i].z, av[i].w};
                    float2 bb0 = smB2[((w * 2 + 0) * 32 + kt) * 32 + lane];
                    float2 bb1 = smB2[((w * 2 + 1) * 32 + kt) * 32 + lane];
                    unsigned br0[2] = {__float_as_uint(bb0.x), __float_as_uint(bb0.y)};
                    unsigned br1[2] = {__float_as_uint(bb1.x), __float_as_uint(bb1.y)};
                    mma_tf32(acc[0], ar, br0);
                    mma_tf32(acc[1], ar, br1);
                }
            }
        }

        // per-warp gate gather (C-fragment -> cells), no block sync
        #pragma unroll
        for (int nt = 0; nt < 2; ++nt)
            #pragma unroll
            for (int q = 0; q < 4; ++q) {
                int col = nt * 8 + ((lane & 3) << 1) + (q & 1);
                int row = (lane >> 2) + ((q & 2) ? 8 : 0);
                myslab[col * 17 + row] = acc[nt][q];
            }
        __syncwarp();

        float h0, h1;
        {
            float g0 = myslab[(p * 4 + 0) * 17 + rloc] + pr[0];
            float g1 = myslab[(p * 4 + 1) * 17 + rloc] + pr[1];
            float g2 = myslab[(p * 4 + 2) * 17 + rloc] + pr[2];
            float g3 = myslab[(p * 4 + 3) * 17 + rloc] + pr[3];
            c0 = sigmoidf_(g1) * c0 + sigmoidf_(g0) * tanh_fast(g2);
            h0 = sigmoidf_(g3) * tanh_fast(c0);
        }
        {
            float g0 = myslab[(p * 4 + 0) * 17 + rloc + 8] + pr[4];
            float g1 = myslab[(p * 4 + 1) * 17 + rloc + 8] + pr[5];
            float g2 = myslab[(p * 4 + 2) * 17 + rloc + 8] + pr[6];
            float g3 = myslab[(p * 4 + 3) * 17 + rloc + 8] + pr[7];
            c1 = sigmoidf_(g1) * c1 + sigmoidf_(g0) * tanh_fast(g2);
            h1 = sigmoidf_(g3) * tanh_fast(c1);
        }

        // publish h(ts+1): tagged tf32 words, single weak L2 store, no sync
        {
            unsigned tagv = (unsigned)(ts + 1);
            unsigned w0 = (f2tf(h0) & 0xFFFFE000u) | tagv;
            unsigned w1 = (f2tf(h1) & 0xFFFFE000u) | tagv;
            stcg_v2(stageD + ((ts + 1) & 1) * 4096 + word0, w0, w1);
        }

        // off-critical-path: g_hs for emissions
        g_hs[(((size_t)dir * SS + t) * BB + b0) * HH + j] = h0;
        g_hs[(((size_t)dir * SS + t) * BB + b1) * HH + j] = h1;

        #pragma unroll
        for (int g = 0; g < 8; ++g) pr[g] = np[g];
    }
}

// ---------------- kernel 5: emissions + NLL partial sums ----------------
__global__ void __launch_bounds__(256) emis_kernel(const int* __restrict__ labels,
                                                   const float* __restrict__ Wtag,
                                                   const float* __restrict__ btag) {
    __shared__ float wt[NTAG * 512];
    __shared__ float bt[NTAG];
    int tid = threadIdx.x;
    for (int i = tid; i < NTAG * 512; i += 256) wt[i] = Wtag[i];
    if (tid < NTAG) bt[tid] = btag[tid];
    __syncthreads();

    int idx = blockIdx.x * 256 + tid;      // 0..8191
    int b = idx >> 8, t = idx & 255;

    float acc[NTAG];
    #pragma unroll
    for (int q = 0; q < NTAG; ++q) acc[q] = bt[q];

    #pragma unroll
    for (int part = 0; part < 2; ++part) {
        const float* hp = g_hs + (((size_t)part * SS + t) * BB + b) * HH;
        for (int k4 = 0; k4 < HH; k4 += 4) {
            float4 h4 = *(const float4*)&hp[k4];
            #pragma unroll
            for (int q = 0; q < NTAG; ++q) {
                const float* w = &wt[q * 512 + part * HH + k4];
                acc[q] += h4.x * w[0] + h4.y * w[1] + h4.z * w[2] + h4.w * w[3];
            }
        }
    }

    int lab = labels[idx];
    float nll = 0.f, cnt = 0.f;
    if (lab != -100) {
        int lc = lab < 0 ? 0 : lab;
        float m = acc[0];
        #pragma unroll
        for (int q = 1; q < NTAG; ++q) m = fmaxf(m, acc[q]);
        float s = 0.f;
        #pragma unroll
        for (int q = 0; q < NTAG; ++q) s += __expf(acc[q] - m);
        nll = m + logf(s) - acc[lc];
        cnt = 1.f;
    }
    #pragma unroll
    for (int off = 16; off; off >>= 1) {
        nll += __shfl_xor_sync(0xffffffffu, nll, off);
        cnt += __shfl_xor_sync(0xffffffffu, cnt, off);
    }
    if ((tid & 31) == 0) {
        atomicAdd(&g_loss_sum, nll);
        atomicAdd(&g_loss_cnt, cnt);
    }
}

// ---------------- kernel 6: finalize ----------------
__global__ void finalize_kernel(float* out) {
    out[0] = g_loss_sum / fmaxf(g_loss_cnt, 1.f);
}

// ---------------- launch ----------------
extern "C" void kernel_launch(void* const* d_in, const int* in_sizes, int n_in,
                              void* d_out, int out_size) {
    const float* word_embs = (const float*)d_in[0];
    const float* char_embs = (const float*)d_in[1];
    const int*   spans     = (const int*)  d_in[2];
    const int*   labels    = (const int*)  d_in[3];
    const float* WihF      = (const float*)d_in[4];
    const float* WhhF      = (const float*)d_in[5];
    const float* bihF      = (const float*)d_in[6];
    const float* bhhF      = (const float*)d_in[7];
    const float* WihB      = (const float*)d_in[8];
    const float* WhhB      = (const float*)d_in[9];
    const float* bihB      = (const float*)d_in[10];
    const float* bhhB      = (const float*)d_in[11];
    const float* Wtag      = (const float*)d_in[12];
    const float* btag      = (const float*)d_in[13];
    float* out = (float*)d_out;

    cudaFuncSetAttribute(fused_kernel, cudaFuncAttributeMaxDynamicSharedMemorySize, FUSED_SMEM_BYTES);

    prep_v_kernel<<<1024, 256>>>(char_embs, spans);
    prep_w_kernel<<<256, 256>>>(WihF, WihB, bihF, bhhF, bihB, bhhB);
    prep_wt_kernel<<<2048, 256>>>(WhhF, WhhB);
    fused_kernel<<<1056, 256, FUSED_SMEM_BYTES>>>(word_embs, WihF, WihB);
    emis_kernel<<<32, 256>>>(labels, Wtag, btag);
    finalize_kernel<<<1, 1>>>(out);
}